// round 7
// baseline (speedup 1.0000x reference)
#include <cuda_runtime.h>
#include <cuda_bf16.h>

#define BATCH 4
#define NPTS  16384
#define MCTR  4096
#define KNB   32
#define R2    0.01f
#define RMARG 0.1005f
#define RM2   (RMARG * RMARG)
#define CH    6
#define NCELL 1000          // 10x10x10 per batch
#define TCELL 4096
#define CAP   128

// Scratch (__device__ globals: allocation-guard-safe, zero-initialized)
__device__ float4 g_pts4 [BATCH * NPTS];     // orig order (x,y,z,p2)
__device__ float4 g_spts4[BATCH * NPTS];     // cell-sorted (x,y,z,p2)
__device__ int    g_sidx [BATCH * NPTS];     // cell-sorted original index
__device__ int    g_cell [BATCH * NPTS];
__device__ int    g_rank [BATCH * NPTS];
__device__ int    g_cnt  [TCELL];            // re-zeroed each pass
__device__ int    g_off  [TCELL + 1];
__device__ int    g_idx  [BATCH * MCTR * KNB];

// ---------------------------------------------------------------------------
__global__ __launch_bounds__(256) void pack_count_kernel(const float* __restrict__ pts) {
    int t = blockIdx.x * blockDim.x + threadIdx.x;
    if (t >= BATCH * NPTS) return;
    int b = t / NPTS, n = t - b * NPTS;
    const float* p = pts + (size_t)b * 3 * NPTS;
    float x = p[n], y = p[NPTS + n], z = p[2 * NPTS + n];
    float p2 = __fmaf_rn(z, z, __fmaf_rn(y, y, __fmul_rn(x, x)));
    g_pts4[t] = make_float4(x, y, z, p2);
    int ci = min(9, max(0, (int)(x * 10.0f)));
    int cj = min(9, max(0, (int)(y * 10.0f)));
    int ck = min(9, max(0, (int)(z * 10.0f)));
    int gc = b * NCELL + (ci * 10 + cj) * 10 + ck;
    g_cell[t] = gc;
    g_rank[t] = atomicAdd(&g_cnt[gc], 1);
}

// exclusive scan over 4096 counts — warp-shuffle 2-level, single block
__global__ __launch_bounds__(1024) void scan_kernel() {
    __shared__ int wsum[32];
    int tid  = threadIdx.x;
    int lane = tid & 31, wid = tid >> 5;

    int i0 = tid * 4;
    int v0 = g_cnt[i0], v1 = g_cnt[i0 + 1], v2 = g_cnt[i0 + 2], v3 = g_cnt[i0 + 3];
    int local = v0 + v1 + v2 + v3;

    int inc = local;
    #pragma unroll
    for (int d = 1; d < 32; d <<= 1) {
        int t = __shfl_up_sync(0xffffffffu, inc, d);
        if (lane >= d) inc += t;
    }
    if (lane == 31) wsum[wid] = inc;
    __syncthreads();
    if (wid == 0) {
        int w = wsum[lane];
        int winc = w;
        #pragma unroll
        for (int d = 1; d < 32; d <<= 1) {
            int t = __shfl_up_sync(0xffffffffu, winc, d);
            if (lane >= d) winc += t;
        }
        wsum[lane] = winc - w;
    }
    __syncthreads();

    int excl = wsum[wid] + inc - local;
    g_off[i0]     = excl;
    g_off[i0 + 1] = excl + v0;
    g_off[i0 + 2] = excl + v0 + v1;
    g_off[i0 + 3] = excl + v0 + v1 + v2;
    if (tid == 1023) g_off[TCELL] = excl + local;
}

// atomic-free scatter; copies (x,y,z,p2), idx to parallel array; re-zeroes g_cnt
__global__ __launch_bounds__(256) void scatter_kernel() {
    int t = blockIdx.x * blockDim.x + threadIdx.x;
    if (t < TCELL) g_cnt[t] = 0;
    if (t >= BATCH * NPTS) return;
    int n = t % NPTS;
    int pos = g_off[g_cell[t]] + g_rank[t];
    g_spts4[pos] = g_pts4[t];
    g_sidx[pos]  = n;
}

// ---------------------------------------------------------------------------
// warp sorting primitives (ascending, 32 elements across lanes)
// ---------------------------------------------------------------------------
__device__ __forceinline__ int sort32(int v, int lane) {
    #pragma unroll
    for (int k = 2; k <= 32; k <<= 1) {
        #pragma unroll
        for (int j = k >> 1; j > 0; j >>= 1) {
            int part = __shfl_xor_sync(0xffffffffu, v, j);
            bool up = ((lane & k) == 0);
            bool takeMin = (((lane & j) == 0) == up);
            v = takeMin ? min(v, part) : max(v, part);
        }
    }
    return v;
}

// a, b ascending -> ascending 32 smallest of the 64-multiset
__device__ __forceinline__ int merge_lower32(int a, int b, int lane) {
    int brev = __shfl_sync(0xffffffffu, b, 31 - lane);
    int m = min(a, brev);                  // bitonic
    #pragma unroll
    for (int j = 16; j > 0; j >>= 1) {     // clean -> ascending
        int part = __shfl_xor_sync(0xffffffffu, m, j);
        bool takeMin = ((lane & j) == 0);
        m = takeMin ? min(m, part) : max(m, part);
    }
    return m;
}

// ---------------------------------------------------------------------------
// warp-per-center query: merged z-spans, column prune, adaptive top-32 select
// ---------------------------------------------------------------------------
__global__ __launch_bounds__(256) void query_kernel(const float* __restrict__ centers) {
    __shared__ int lists[8][CAP];
    int gw   = (blockIdx.x * blockDim.x + threadIdx.x) >> 5;
    int wslt = threadIdx.x >> 5;
    int lane = threadIdx.x & 31;
    int b = gw / MCTR, m = gw - b * MCTR;

    const float* c = centers + (size_t)b * 3 * MCTR;
    float cx = c[m], cy = c[MCTR + m], cz = c[2 * MCTR + m];
    float c2 = __fmaf_rn(cz, cz, __fmaf_rn(cy, cy, __fmul_rn(cx, cx)));

    int i0 = max(0, (int)((cx - RMARG) * 10.0f)), i1 = min(9, (int)((cx + RMARG) * 10.0f));
    int j0 = max(0, (int)((cy - RMARG) * 10.0f)), j1 = min(9, (int)((cy + RMARG) * 10.0f));
    int k0 = max(0, (int)((cz - RMARG) * 10.0f)), k1 = min(9, (int)((cz + RMARG) * 10.0f));

    int* lst = lists[wslt];
    unsigned below = (1u << lane) - 1u;
    unsigned cnt = 0;

    for (int ci = i0; ci <= i1; ci++) {
        float lox = ci * 0.1f, hix = lox + 0.1f;
        float dxm = fmaxf(fmaxf(lox - cx, cx - hix), 0.0f);
        float dx2 = dxm * dxm;
        for (int cj = j0; cj <= j1; cj++) {
            float loy = cj * 0.1f, hiy = loy + 0.1f;
            float dym = fmaxf(fmaxf(loy - cy, cy - hiy), 0.0f);
            if (__fmaf_rn(dym, dym, dx2) >= RM2) continue;   // column prune

            int cb = b * NCELL + (ci * 10 + cj) * 10;
            int start = g_off[cb + k0];
            int end   = g_off[cb + k1 + 1];
            for (int pb = start; pb < end; pb += 32) {
                int p = pb + lane;
                bool hit = false;
                if (p < end) {
                    float4 q = g_spts4[p];
                    float cp = __fmaf_rn(cz, q.z, __fmaf_rn(cy, q.y, __fmul_rn(cx, q.x)));
                    float d2 = __fsub_rn(__fadd_rn(c2, q.w), __fmul_rn(2.0f, cp));
                    hit = d2 < R2;
                }
                unsigned msk = __ballot_sync(0xffffffffu, hit);
                unsigned pos = cnt + __popc(msk & below);
                if (hit && pos < CAP) lst[pos] = g_sidx[p];
                cnt += __popc(msk);
            }
        }
    }

    int eff = min((int)cnt, CAP);
    for (int t = eff + lane; t < CAP; t += 32) lst[t] = 0x7fffffff;
    __syncwarp();

    // adaptive top-32 selection (eff is warp-uniform)
    int top;
    {
        int a = sort32(lst[lane], lane);
        if (eff <= 32) {
            top = a;
        } else {
            int bb = sort32(lst[32 + lane], lane);
            int m01 = merge_lower32(a, bb, lane);
            if (eff <= 64) {
                top = m01;
            } else {
                int cc = sort32(lst[64 + lane], lane);
                if (eff <= 96) {
                    top = merge_lower32(m01, cc, lane);
                } else {
                    int dd = sort32(lst[96 + lane], lane);
                    top = merge_lower32(m01, merge_lower32(cc, dd, lane), lane);
                }
            }
        }
    }

    g_idx[(size_t)gw * KNB + lane] = (lane < eff) ? top : 0;
}

// ---------------------------------------------------------------------------
// tiled gather: 32 centers/block, MLP-4 random loads, coalesced writes along m
// ---------------------------------------------------------------------------
__global__ __launch_bounds__(256) void gather_kernel(const float* __restrict__ centers,
                                                     float* __restrict__ out) {
    __shared__ int   idx_s[32][33];
    __shared__ float cs[3][32];

    int b  = blockIdx.y;
    int m0 = blockIdx.x * 32;
    int tid = threadIdx.x;

    for (int t = tid; t < 32 * 32; t += 256) {
        int ml = t >> 5, k = t & 31;
        idx_s[ml][k] = g_idx[((size_t)(b * MCTR + m0 + ml)) * KNB + k];
    }
    if (tid < 96) {
        int coord = tid / 32, ml = tid - coord * 32;
        cs[coord][ml] = centers[(size_t)b * 3 * MCTR + coord * MCTR + m0 + ml];
    }
    __syncthreads();

    int w = tid >> 5, lane = tid & 31;
    const float4* __restrict__ pts = g_pts4 + (size_t)b * NPTS;
    float cx = cs[0][lane], cy = cs[1][lane], cz = cs[2][lane];

    float* ob = out + (size_t)b * (CH * KNB) * MCTR + m0 + lane;

    int ns[4];
    #pragma unroll
    for (int j = 0; j < 4; j++) ns[j] = idx_s[lane][w + j * 8];
    float4 p[4];
    #pragma unroll
    for (int j = 0; j < 4; j++) p[j] = __ldg(&pts[ns[j]]);

    #pragma unroll
    for (int j = 0; j < 4; j++) {
        int k = w + j * 8;
        float* o = ob + (size_t)k * MCTR;
        o[(size_t)0 * KNB * MCTR] = p[j].x;
        o[(size_t)1 * KNB * MCTR] = p[j].y;
        o[(size_t)2 * KNB * MCTR] = p[j].z;
        o[(size_t)3 * KNB * MCTR] = __fsub_rn(p[j].x, cx);
        o[(size_t)4 * KNB * MCTR] = __fsub_rn(p[j].y, cy);
        o[(size_t)5 * KNB * MCTR] = __fsub_rn(p[j].z, cz);
    }
}

// ---------------------------------------------------------------------------
extern "C" void kernel_launch(void* const* d_in, const int* in_sizes, int n_in,
                              void* d_out, int out_size) {
    const float* pts = (const float*)d_in[0];
    const float* ctr = (const float*)d_in[1];
    if (n_in >= 2 && in_sizes[0] < in_sizes[1]) {
        const float* t = pts; pts = ctr; ctr = t;
    }
    float* out = (float*)d_out;

    pack_count_kernel<<<(BATCH * NPTS) / 256, 256>>>(pts);
    scan_kernel<<<1, 1024>>>();
    scatter_kernel<<<(BATCH * NPTS) / 256, 256>>>();
    query_kernel<<<(BATCH * MCTR) / 8, 256>>>(ctr);
    dim3 ggrid(MCTR / 32, BATCH);
    gather_kernel<<<ggrid, 256>>>(ctr, out);
}

// round 8
// speedup vs baseline: 1.0437x; 1.0437x over previous
#include <cuda_runtime.h>
#include <cuda_bf16.h>

#define BATCH 4
#define NPTS  16384
#define MCTR  4096
#define KNB   32
#define R2    0.01f
#define RMARG 0.1005f
#define RM2   (RMARG * RMARG)
#define CH    6
#define NCELL 1000          // 10x10x10 per batch
#define TCELL 4096
#define CAP   128

// Scratch (__device__ globals: allocation-guard-safe, zero-initialized)
__device__ float4 g_pts4 [BATCH * NPTS];     // orig order (x,y,z,p2)
__device__ float4 g_spts4[BATCH * NPTS];     // cell-sorted (x,y,z,bitcast idx)
__device__ int    g_cell [BATCH * NPTS];
__device__ int    g_rank [BATCH * NPTS];
__device__ int    g_cnt  [TCELL];            // re-zeroed each pass
__device__ int    g_off  [TCELL + 1];
__device__ int    g_idx  [BATCH * MCTR * KNB];

// ---------------------------------------------------------------------------
__global__ __launch_bounds__(256) void pack_count_kernel(const float* __restrict__ pts) {
    int t = blockIdx.x * blockDim.x + threadIdx.x;
    if (t >= BATCH * NPTS) return;
    int b = t / NPTS, n = t - b * NPTS;
    const float* p = pts + (size_t)b * 3 * NPTS;
    float x = p[n], y = p[NPTS + n], z = p[2 * NPTS + n];
    float p2 = __fmaf_rn(z, z, __fmaf_rn(y, y, __fmul_rn(x, x)));
    g_pts4[t] = make_float4(x, y, z, p2);
    int ci = min(9, max(0, (int)(x * 10.0f)));
    int cj = min(9, max(0, (int)(y * 10.0f)));
    int ck = min(9, max(0, (int)(z * 10.0f)));
    int gc = b * NCELL + (ci * 10 + cj) * 10 + ck;
    g_cell[t] = gc;
    g_rank[t] = atomicAdd(&g_cnt[gc], 1);
}

// exclusive scan over 4096 counts — warp-shuffle 2-level, single block
__global__ __launch_bounds__(1024) void scan_kernel() {
    __shared__ int wsum[32];
    int tid  = threadIdx.x;
    int lane = tid & 31, wid = tid >> 5;

    int i0 = tid * 4;
    int v0 = g_cnt[i0], v1 = g_cnt[i0 + 1], v2 = g_cnt[i0 + 2], v3 = g_cnt[i0 + 3];
    int local = v0 + v1 + v2 + v3;

    int inc = local;
    #pragma unroll
    for (int d = 1; d < 32; d <<= 1) {
        int t = __shfl_up_sync(0xffffffffu, inc, d);
        if (lane >= d) inc += t;
    }
    if (lane == 31) wsum[wid] = inc;
    __syncthreads();
    if (wid == 0) {
        int w = wsum[lane];
        int winc = w;
        #pragma unroll
        for (int d = 1; d < 32; d <<= 1) {
            int t = __shfl_up_sync(0xffffffffu, winc, d);
            if (lane >= d) winc += t;
        }
        wsum[lane] = winc - w;
    }
    __syncthreads();

    int excl = wsum[wid] + inc - local;
    g_off[i0]     = excl;
    g_off[i0 + 1] = excl + v0;
    g_off[i0 + 2] = excl + v0 + v1;
    g_off[i0 + 3] = excl + v0 + v1 + v2;
    if (tid == 1023) g_off[TCELL] = excl + local;
}

// atomic-free scatter into cell-sorted dense array (idx in .w); re-zeroes g_cnt
__global__ __launch_bounds__(256) void scatter_kernel() {
    int t = blockIdx.x * blockDim.x + threadIdx.x;
    if (t < TCELL) g_cnt[t] = 0;
    if (t >= BATCH * NPTS) return;
    int n = t % NPTS;
    int pos = g_off[g_cell[t]] + g_rank[t];
    float4 p = g_pts4[t];
    g_spts4[pos] = make_float4(p.x, p.y, p.z, __int_as_float(n));
}

// ---------------------------------------------------------------------------
// warp selection primitives (ascending, 32 elements across lanes)
// ---------------------------------------------------------------------------
__device__ __forceinline__ int sort32(int v, int lane) {
    #pragma unroll
    for (int k = 2; k <= 32; k <<= 1) {
        #pragma unroll
        for (int j = k >> 1; j > 0; j >>= 1) {
            int part = __shfl_xor_sync(0xffffffffu, v, j);
            bool up = ((lane & k) == 0);
            bool takeMin = (((lane & j) == 0) == up);
            v = takeMin ? min(v, part) : max(v, part);
        }
    }
    return v;
}

// a, b ascending -> ascending 32 smallest of the 64-multiset
__device__ __forceinline__ int merge_lower32(int a, int b, int lane) {
    int brev = __shfl_sync(0xffffffffu, b, 31 - lane);
    int m = min(a, brev);                  // bitonic
    #pragma unroll
    for (int j = 16; j > 0; j >>= 1) {     // clean -> ascending
        int part = __shfl_xor_sync(0xffffffffu, m, j);
        bool takeMin = ((lane & j) == 0);
        m = takeMin ? min(m, part) : max(m, part);
    }
    return m;
}

// ---------------------------------------------------------------------------
// warp-per-center query: merged z-spans, column prune, adaptive top-32 select
// ---------------------------------------------------------------------------
__global__ __launch_bounds__(256) void query_kernel(const float* __restrict__ centers) {
    __shared__ int lists[8][CAP];
    int gw   = (blockIdx.x * blockDim.x + threadIdx.x) >> 5;
    int wslt = threadIdx.x >> 5;
    int lane = threadIdx.x & 31;
    int b = gw / MCTR, m = gw - b * MCTR;

    const float* c = centers + (size_t)b * 3 * MCTR;
    float cx = c[m], cy = c[MCTR + m], cz = c[2 * MCTR + m];
    float c2 = __fmaf_rn(cz, cz, __fmaf_rn(cy, cy, __fmul_rn(cx, cx)));

    int i0 = max(0, (int)((cx - RMARG) * 10.0f)), i1 = min(9, (int)((cx + RMARG) * 10.0f));
    int j0 = max(0, (int)((cy - RMARG) * 10.0f)), j1 = min(9, (int)((cy + RMARG) * 10.0f));
    int k0 = max(0, (int)((cz - RMARG) * 10.0f)), k1 = min(9, (int)((cz + RMARG) * 10.0f));

    int* lst = lists[wslt];
    unsigned below = (1u << lane) - 1u;
    unsigned cnt = 0;

    for (int ci = i0; ci <= i1; ci++) {
        float lox = ci * 0.1f, hix = lox + 0.1f;
        float dxm = fmaxf(fmaxf(lox - cx, cx - hix), 0.0f);
        float dx2 = dxm * dxm;
        for (int cj = j0; cj <= j1; cj++) {
            float loy = cj * 0.1f, hiy = loy + 0.1f;
            float dym = fmaxf(fmaxf(loy - cy, cy - hiy), 0.0f);
            if (__fmaf_rn(dym, dym, dx2) >= RM2) continue;   // column prune

            int cb = b * NCELL + (ci * 10 + cj) * 10;        // z-cells contiguous
            int start = g_off[cb + k0];
            int end   = g_off[cb + k1 + 1];
            for (int pb = start; pb < end; pb += 32) {
                int p = pb + lane;
                bool hit = false; int idxv = 0;
                if (p < end) {
                    float4 q = g_spts4[p];
                    float p2 = __fmaf_rn(q.z, q.z, __fmaf_rn(q.y, q.y, __fmul_rn(q.x, q.x)));
                    float cp = __fmaf_rn(cz, q.z, __fmaf_rn(cy, q.y, __fmul_rn(cx, q.x)));
                    float d2 = __fsub_rn(__fadd_rn(c2, p2), __fmul_rn(2.0f, cp));
                    hit = d2 < R2;
                    idxv = __float_as_int(q.w);
                }
                unsigned msk = __ballot_sync(0xffffffffu, hit);
                unsigned pos = cnt + __popc(msk & below);
                if (hit && pos < CAP) lst[pos] = idxv;
                cnt += __popc(msk);
            }
        }
    }

    int eff = min((int)cnt, CAP);
    int ng  = (eff <= 32) ? 1 : (eff <= 64) ? 2 : (eff <= 96) ? 3 : 4;
    for (int t = eff + lane; t < ng * 32; t += 32) lst[t] = 0x7fffffff;
    __syncwarp();

    // adaptive top-32 selection (eff warp-uniform; sorted ascending)
    int top;
    {
        int a = sort32(lst[lane], lane);
        if (ng == 1) {
            top = a;
        } else {
            int bb = sort32(lst[32 + lane], lane);
            int m01 = merge_lower32(a, bb, lane);
            if (ng == 2) {
                top = m01;
            } else {
                int cc = sort32(lst[64 + lane], lane);
                if (ng == 3) {
                    top = merge_lower32(m01, cc, lane);
                } else {
                    int dd = sort32(lst[96 + lane], lane);
                    top = merge_lower32(m01, merge_lower32(cc, dd, lane), lane);
                }
            }
        }
    }

    g_idx[(size_t)gw * KNB + lane] = (lane < eff) ? top : 0;
}

// ---------------------------------------------------------------------------
// tiled gather: 32 centers/block, MLP-4 random loads, coalesced writes along m
// ---------------------------------------------------------------------------
__global__ __launch_bounds__(256) void gather_kernel(const float* __restrict__ centers,
                                                     float* __restrict__ out) {
    __shared__ int   idx_s[32][33];
    __shared__ float cs[3][32];

    int b  = blockIdx.y;
    int m0 = blockIdx.x * 32;
    int tid = threadIdx.x;

    for (int t = tid; t < 32 * 32; t += 256) {
        int ml = t >> 5, k = t & 31;
        idx_s[ml][k] = g_idx[((size_t)(b * MCTR + m0 + ml)) * KNB + k];
    }
    if (tid < 96) {
        int coord = tid / 32, ml = tid - coord * 32;
        cs[coord][ml] = centers[(size_t)b * 3 * MCTR + coord * MCTR + m0 + ml];
    }
    __syncthreads();

    int w = tid >> 5, lane = tid & 31;
    const float4* __restrict__ pts = g_pts4 + (size_t)b * NPTS;
    float cx = cs[0][lane], cy = cs[1][lane], cz = cs[2][lane];

    float* ob = out + (size_t)b * (CH * KNB) * MCTR + m0 + lane;

    int ns[4];
    #pragma unroll
    for (int j = 0; j < 4; j++) ns[j] = idx_s[lane][w + j * 8];
    float4 p[4];
    #pragma unroll
    for (int j = 0; j < 4; j++) p[j] = __ldg(&pts[ns[j]]);

    #pragma unroll
    for (int j = 0; j < 4; j++) {
        int k = w + j * 8;
        float* o = ob + (size_t)k * MCTR;
        o[(size_t)0 * KNB * MCTR] = p[j].x;
        o[(size_t)1 * KNB * MCTR] = p[j].y;
        o[(size_t)2 * KNB * MCTR] = p[j].z;
        o[(size_t)3 * KNB * MCTR] = __fsub_rn(p[j].x, cx);
        o[(size_t)4 * KNB * MCTR] = __fsub_rn(p[j].y, cy);
        o[(size_t)5 * KNB * MCTR] = __fsub_rn(p[j].z, cz);
    }
}

// ---------------------------------------------------------------------------
extern "C" void kernel_launch(void* const* d_in, const int* in_sizes, int n_in,
                              void* d_out, int out_size) {
    const float* pts = (const float*)d_in[0];
    const float* ctr = (const float*)d_in[1];
    if (n_in >= 2 && in_sizes[0] < in_sizes[1]) {
        const float* t = pts; pts = ctr; ctr = t;
    }
    float* out = (float*)d_out;

    pack_count_kernel<<<(BATCH * NPTS) / 256, 256>>>(pts);
    scan_kernel<<<1, 1024>>>();
    scatter_kernel<<<(BATCH * NPTS) / 256, 256>>>();
    query_kernel<<<(BATCH * MCTR) / 8, 256>>>(ctr);
    dim3 ggrid(MCTR / 32, BATCH);
    gather_kernel<<<ggrid, 256>>>(ctr, out);
}

// round 9
// speedup vs baseline: 1.0839x; 1.0385x over previous
#include <cuda_runtime.h>
#include <cuda_bf16.h>

#define BATCH 4
#define NPTS  16384
#define MCTR  4096
#define KNB   32
#define R2    0.01f
#define RMARG 0.1005f
#define RM2   (RMARG * RMARG)
#define CH    6
#define NCELL 1000          // 10x10x10 per batch
#define TCELL 4096
#define CAP   128

// Scratch (__device__ globals: allocation-guard-safe, zero-initialized)
__device__ float4 g_pts4 [BATCH * NPTS];     // orig order (x,y,z,p2)
__device__ float4 g_spts4[BATCH * NPTS];     // cell-sorted (x,y,z,bitcast idx)
__device__ int    g_cell [BATCH * NPTS];
__device__ int    g_rank [BATCH * NPTS];
__device__ int    g_cnt  [TCELL];            // re-zeroed each pass
__device__ int    g_off  [TCELL + 1];
__device__ int    g_idx  [BATCH * MCTR * KNB];

// ---------------------------------------------------------------------------
__global__ __launch_bounds__(256) void pack_count_kernel(const float* __restrict__ pts) {
    int t = blockIdx.x * blockDim.x + threadIdx.x;
    if (t >= BATCH * NPTS) return;
    int b = t / NPTS, n = t - b * NPTS;
    const float* p = pts + (size_t)b * 3 * NPTS;
    float x = p[n], y = p[NPTS + n], z = p[2 * NPTS + n];
    float p2 = __fmaf_rn(z, z, __fmaf_rn(y, y, __fmul_rn(x, x)));
    g_pts4[t] = make_float4(x, y, z, p2);
    int ci = min(9, max(0, (int)(x * 10.0f)));
    int cj = min(9, max(0, (int)(y * 10.0f)));
    int ck = min(9, max(0, (int)(z * 10.0f)));
    int gc = b * NCELL + (ci * 10 + cj) * 10 + ck;
    g_cell[t] = gc;
    g_rank[t] = atomicAdd(&g_cnt[gc], 1);
}

// exclusive scan over 4096 counts — warp-shuffle 2-level, single block
__global__ __launch_bounds__(1024) void scan_kernel() {
    __shared__ int wsum[32];
    int tid  = threadIdx.x;
    int lane = tid & 31, wid = tid >> 5;

    int i0 = tid * 4;
    int v0 = g_cnt[i0], v1 = g_cnt[i0 + 1], v2 = g_cnt[i0 + 2], v3 = g_cnt[i0 + 3];
    int local = v0 + v1 + v2 + v3;

    int inc = local;
    #pragma unroll
    for (int d = 1; d < 32; d <<= 1) {
        int t = __shfl_up_sync(0xffffffffu, inc, d);
        if (lane >= d) inc += t;
    }
    if (lane == 31) wsum[wid] = inc;
    __syncthreads();
    if (wid == 0) {
        int w = wsum[lane];
        int winc = w;
        #pragma unroll
        for (int d = 1; d < 32; d <<= 1) {
            int t = __shfl_up_sync(0xffffffffu, winc, d);
            if (lane >= d) winc += t;
        }
        wsum[lane] = winc - w;
    }
    __syncthreads();

    int excl = wsum[wid] + inc - local;
    g_off[i0]     = excl;
    g_off[i0 + 1] = excl + v0;
    g_off[i0 + 2] = excl + v0 + v1;
    g_off[i0 + 3] = excl + v0 + v1 + v2;
    if (tid == 1023) g_off[TCELL] = excl + local;
}

// atomic-free scatter into cell-sorted dense array (idx in .w); re-zeroes g_cnt
__global__ __launch_bounds__(256) void scatter_kernel() {
    int t = blockIdx.x * blockDim.x + threadIdx.x;
    if (t < TCELL) g_cnt[t] = 0;
    if (t >= BATCH * NPTS) return;
    int n = t % NPTS;
    int pos = g_off[g_cell[t]] + g_rank[t];
    float4 p = g_pts4[t];
    g_spts4[pos] = make_float4(p.x, p.y, p.z, __int_as_float(n));
}

// ---------------------------------------------------------------------------
// warp selection primitives (ascending, 32 elements across lanes)
// ---------------------------------------------------------------------------
__device__ __forceinline__ int sort32(int v, int lane) {
    #pragma unroll
    for (int k = 2; k <= 32; k <<= 1) {
        #pragma unroll
        for (int j = k >> 1; j > 0; j >>= 1) {
            int part = __shfl_xor_sync(0xffffffffu, v, j);
            bool up = ((lane & k) == 0);
            bool takeMin = (((lane & j) == 0) == up);
            v = takeMin ? min(v, part) : max(v, part);
        }
    }
    return v;
}

// a, b ascending -> ascending 32 smallest of the 64-multiset
__device__ __forceinline__ int merge_lower32(int a, int b, int lane) {
    int brev = __shfl_sync(0xffffffffu, b, 31 - lane);
    int m = min(a, brev);                  // bitonic
    #pragma unroll
    for (int j = 16; j > 0; j >>= 1) {     // clean -> ascending
        int part = __shfl_xor_sync(0xffffffffu, m, j);
        bool takeMin = ((lane & j) == 0);
        m = takeMin ? min(m, part) : max(m, part);
    }
    return m;
}

// ---------------------------------------------------------------------------
// warp-per-center query: 64-pt iterations, column prune, adaptive top-32 select
// ---------------------------------------------------------------------------
__global__ __launch_bounds__(256) void query_kernel(const float* __restrict__ centers) {
    __shared__ int lists[8][CAP];
    int gw   = (blockIdx.x * blockDim.x + threadIdx.x) >> 5;
    int wslt = threadIdx.x >> 5;
    int lane = threadIdx.x & 31;
    int b = gw / MCTR, m = gw - b * MCTR;

    const float* c = centers + (size_t)b * 3 * MCTR;
    float cx = c[m], cy = c[MCTR + m], cz = c[2 * MCTR + m];
    float c2 = __fmaf_rn(cz, cz, __fmaf_rn(cy, cy, __fmul_rn(cx, cx)));

    int i0 = max(0, (int)((cx - RMARG) * 10.0f)), i1 = min(9, (int)((cx + RMARG) * 10.0f));
    int j0 = max(0, (int)((cy - RMARG) * 10.0f)), j1 = min(9, (int)((cy + RMARG) * 10.0f));
    int k0 = max(0, (int)((cz - RMARG) * 10.0f)), k1 = min(9, (int)((cz + RMARG) * 10.0f));

    int* lst = lists[wslt];
    unsigned below = (1u << lane) - 1u;
    unsigned cnt = 0;

    for (int ci = i0; ci <= i1; ci++) {
        float lox = ci * 0.1f, hix = lox + 0.1f;
        float dxm = fmaxf(fmaxf(lox - cx, cx - hix), 0.0f);
        float dx2 = dxm * dxm;
        for (int cj = j0; cj <= j1; cj++) {
            float loy = cj * 0.1f, hiy = loy + 0.1f;
            float dym = fmaxf(fmaxf(loy - cy, cy - hiy), 0.0f);
            if (__fmaf_rn(dym, dym, dx2) >= RM2) continue;   // column prune

            int cb = b * NCELL + (ci * 10 + cj) * 10;        // z-cells contiguous
            int start = g_off[cb + k0];
            int end   = g_off[cb + k1 + 1];
            for (int pb = start; pb < end; pb += 64) {
                int p0 = pb + lane;
                int p1 = pb + 32 + lane;
                bool h0 = false, h1 = false;
                int iv0 = 0, iv1 = 0;
                // both loads issued up front (MLP=2)
                if (p0 < end) {
                    float4 q = g_spts4[p0];
                    float p2 = __fmaf_rn(q.z, q.z, __fmaf_rn(q.y, q.y, __fmul_rn(q.x, q.x)));
                    float cp = __fmaf_rn(cz, q.z, __fmaf_rn(cy, q.y, __fmul_rn(cx, q.x)));
                    float d2 = __fsub_rn(__fadd_rn(c2, p2), __fmul_rn(2.0f, cp));
                    h0 = d2 < R2;
                    iv0 = __float_as_int(q.w);
                }
                if (p1 < end) {
                    float4 q = g_spts4[p1];
                    float p2 = __fmaf_rn(q.z, q.z, __fmaf_rn(q.y, q.y, __fmul_rn(q.x, q.x)));
                    float cp = __fmaf_rn(cz, q.z, __fmaf_rn(cy, q.y, __fmul_rn(cx, q.x)));
                    float d2 = __fsub_rn(__fadd_rn(c2, p2), __fmul_rn(2.0f, cp));
                    h1 = d2 < R2;
                    iv1 = __float_as_int(q.w);
                }
                unsigned m0 = __ballot_sync(0xffffffffu, h0);
                unsigned m1 = __ballot_sync(0xffffffffu, h1);

                unsigned s0 = cnt + __popc(m0 & below);
                if (h0 && s0 < CAP) lst[s0] = iv0;
                unsigned cmid = cnt + __popc(m0);
                unsigned s1 = cmid + __popc(m1 & below);
                if (h1 && s1 < CAP) lst[s1] = iv1;
                cnt = cmid + __popc(m1);
            }
        }
    }

    int eff = min((int)cnt, CAP);
    int ng  = (eff <= 32) ? 1 : (eff <= 64) ? 2 : (eff <= 96) ? 3 : 4;
    for (int t = eff + lane; t < ng * 32; t += 32) lst[t] = 0x7fffffff;
    __syncwarp();

    // adaptive top-32 selection (eff warp-uniform; result ascending)
    int top;
    {
        int a = sort32(lst[lane], lane);
        if (ng == 1) {
            top = a;
        } else {
            int bb = sort32(lst[32 + lane], lane);
            int m01 = merge_lower32(a, bb, lane);
            if (ng == 2) {
                top = m01;
            } else {
                int cc = sort32(lst[64 + lane], lane);
                if (ng == 3) {
                    top = merge_lower32(m01, cc, lane);
                } else {
                    int dd = sort32(lst[96 + lane], lane);
                    top = merge_lower32(m01, merge_lower32(cc, dd, lane), lane);
                }
            }
        }
    }

    g_idx[(size_t)gw * KNB + lane] = (lane < eff) ? top : 0;
}

// ---------------------------------------------------------------------------
// tiled gather: 32 centers/block, thread owns a 4-m quad for one k,
// 6 STG.128 per thread, fully coalesced
// ---------------------------------------------------------------------------
__global__ __launch_bounds__(256) void gather_kernel(const float* __restrict__ centers,
                                                     float* __restrict__ out) {
    __shared__ __align__(16) int   idx_s[32][36];   // [k][m], 144B rows
    __shared__ __align__(16) float cs[3][32];

    int b  = blockIdx.y;
    int m0 = blockIdx.x * 32;
    int tid = threadIdx.x;

    // load 32x32 index tile transposed to [k][m]
    for (int t = tid; t < 32 * 32; t += 256) {
        int ml = t >> 5, k = t & 31;
        idx_s[k][ml] = g_idx[((size_t)(b * MCTR + m0 + ml)) * KNB + k];
    }
    if (tid < 96) {
        int coord = tid / 32, ml = tid - coord * 32;
        cs[coord][ml] = centers[(size_t)b * 3 * MCTR + coord * MCTR + m0 + ml];
    }
    __syncthreads();

    int lane = tid & 31, wid = tid >> 5;
    int k    = (wid << 2) | (lane >> 3);   // 0..31
    int quad = (lane & 7) << 2;            // m offset within tile: 0,4,...,28

    const float4* __restrict__ pts = g_pts4 + (size_t)b * NPTS;

    int4 ni = *reinterpret_cast<const int4*>(&idx_s[k][quad]);
    float4 p0 = __ldg(&pts[ni.x]);
    float4 p1 = __ldg(&pts[ni.y]);
    float4 p2 = __ldg(&pts[ni.z]);
    float4 p3 = __ldg(&pts[ni.w]);

    float4 cxq = *reinterpret_cast<const float4*>(&cs[0][quad]);
    float4 cyq = *reinterpret_cast<const float4*>(&cs[1][quad]);
    float4 czq = *reinterpret_cast<const float4*>(&cs[2][quad]);

    float* o = out + (size_t)b * (CH * KNB) * MCTR + (size_t)k * MCTR + m0 + quad;
    const size_t CHS = (size_t)KNB * MCTR;

    float4 vx = make_float4(p0.x, p1.x, p2.x, p3.x);
    float4 vy = make_float4(p0.y, p1.y, p2.y, p3.y);
    float4 vz = make_float4(p0.z, p1.z, p2.z, p3.z);
    float4 rx = make_float4(__fsub_rn(p0.x, cxq.x), __fsub_rn(p1.x, cxq.y),
                            __fsub_rn(p2.x, cxq.z), __fsub_rn(p3.x, cxq.w));
    float4 ry = make_float4(__fsub_rn(p0.y, cyq.x), __fsub_rn(p1.y, cyq.y),
                            __fsub_rn(p2.y, cyq.z), __fsub_rn(p3.y, cyq.w));
    float4 rz = make_float4(__fsub_rn(p0.z, czq.x), __fsub_rn(p1.z, czq.y),
                            __fsub_rn(p2.z, czq.z), __fsub_rn(p3.z, czq.w));

    *reinterpret_cast<float4*>(o + 0 * CHS) = vx;
    *reinterpret_cast<float4*>(o + 1 * CHS) = vy;
    *reinterpret_cast<float4*>(o + 2 * CHS) = vz;
    *reinterpret_cast<float4*>(o + 3 * CHS) = rx;
    *reinterpret_cast<float4*>(o + 4 * CHS) = ry;
    *reinterpret_cast<float4*>(o + 5 * CHS) = rz;
}

// ---------------------------------------------------------------------------
extern "C" void kernel_launch(void* const* d_in, const int* in_sizes, int n_in,
                              void* d_out, int out_size) {
    const float* pts = (const float*)d_in[0];
    const float* ctr = (const float*)d_in[1];
    if (n_in >= 2 && in_sizes[0] < in_sizes[1]) {
        const float* t = pts; pts = ctr; ctr = t;
    }
    float* out = (float*)d_out;

    pack_count_kernel<<<(BATCH * NPTS) / 256, 256>>>(pts);
    scan_kernel<<<1, 1024>>>();
    scatter_kernel<<<(BATCH * NPTS) / 256, 256>>>();
    query_kernel<<<(BATCH * MCTR) / 8, 256>>>(ctr);
    dim3 ggrid(MCTR / 32, BATCH);
    gather_kernel<<<ggrid, 256>>>(ctr, out);
}